// round 2
// baseline (speedup 1.0000x reference)
#include <cuda_runtime.h>
#include <cuda_bf16.h>
#include <cstdint>

// Problem constants
#define BB 32
#define LL 512
#define DD 384
#define KK 3

// Conv tiling
#define BL 64      // L-tile per block
#define BCO 128    // c_out tile per block
#define BK 16      // c_in chunk
#define NTHREADS 256

// Ping-pong intermediates (allocation-free scratch)
__device__ float g_buf0[BB * LL * DD];
__device__ float g_buf1[BB * LL * DD];
__device__ int   g_cum[BB * LL];
__device__ int   g_total[BB];

// ---------------------------------------------------------------------------
// Conv1D (K=3, SAME) + bias + ReLU as a register-blocked tiled GEMM.
// x: [B, L, D] row-major; w: [Cout, Cin, 3]; y: [B, L, D]
// Block computes a [BL x BCO] output tile for one batch.
// Thread tile: 4 L-positions x 8 c_out.
// ---------------------------------------------------------------------------
__global__ __launch_bounds__(NTHREADS) void conv_relu_kernel(
    const float* __restrict__ x, const float* __restrict__ w,
    const float* __restrict__ bias, float* __restrict__ y)
{
    __shared__ float As[BK][BL + 4];        // [ci][row], rows 0..65 (halo), pad
    __shared__ float Ws[BK][BCO * 3];       // [ci][co*3 + k]

    const int b   = blockIdx.z;
    const int l0  = blockIdx.x * BL;
    const int co0 = blockIdx.y * BCO;
    const int tid = threadIdx.x;
    const int tr  = tid >> 4;               // 0..15  -> L rows
    const int tc  = tid & 15;               // 0..15  -> c_out groups
    const int lr  = tr * 4;
    const int cr  = tc * 8;

    float acc[4][8];
#pragma unroll
    for (int i = 0; i < 4; i++)
#pragma unroll
        for (int j = 0; j < 8; j++) acc[i][j] = 0.f;

    for (int k0 = 0; k0 < DD; k0 += BK) {
        // ---- load x tile with halo: rows 0..65 map to l = l0-1+r ----
        for (int idx = tid; idx < 66 * BK; idx += NTHREADS) {
            int r  = idx >> 4;              // 0..65
            int ci = idx & (BK - 1);
            int l  = l0 - 1 + r;
            float v = 0.f;
            if (l >= 0 && l < LL) v = x[((size_t)(b * LL + l)) * DD + k0 + ci];
            As[ci][r] = v;
        }
        // ---- load weight tile: [BCO co][BK ci][3 k] ----
        for (int idx = tid; idx < BCO * BK * 3; idx += NTHREADS) {
            int co  = idx / (BK * 3);
            int rem = idx - co * (BK * 3);
            int ci  = rem / 3;
            int k   = rem - ci * 3;
            Ws[ci][co * 3 + k] = w[(size_t)(co0 + co) * (DD * 3) + (k0 + ci) * 3 + k];
        }
        __syncthreads();

#pragma unroll 4
        for (int ci = 0; ci < BK; ci++) {
            float a[6];
            const float* ap = &As[ci][lr];
#pragma unroll
            for (int j = 0; j < 6; j++) a[j] = ap[j];
            float bw[24];
            const float* wp = &Ws[ci][cr * 3];
#pragma unroll
            for (int j = 0; j < 24; j++) bw[j] = wp[j];
#pragma unroll
            for (int li = 0; li < 4; li++)
#pragma unroll
                for (int cj = 0; cj < 8; cj++)
#pragma unroll
                    for (int k = 0; k < 3; k++)
                        acc[li][cj] = fmaf(a[li + k], bw[cj * 3 + k], acc[li][cj]);
        }
        __syncthreads();
    }

    // ---- epilogue: bias + ReLU, vectorized stores ----
    float bs[8];
#pragma unroll
    for (int cj = 0; cj < 8; cj++) bs[cj] = bias[co0 + cr + cj];

#pragma unroll
    for (int li = 0; li < 4; li++) {
        int l = l0 + lr + li;
        float* yp = &y[((size_t)(b * LL + l)) * DD + co0 + cr];
        float4 v0, v1;
        v0.x = fmaxf(acc[li][0] + bs[0], 0.f);
        v0.y = fmaxf(acc[li][1] + bs[1], 0.f);
        v0.z = fmaxf(acc[li][2] + bs[2], 0.f);
        v0.w = fmaxf(acc[li][3] + bs[3], 0.f);
        v1.x = fmaxf(acc[li][4] + bs[4], 0.f);
        v1.y = fmaxf(acc[li][5] + bs[5], 0.f);
        v1.z = fmaxf(acc[li][6] + bs[6], 0.f);
        v1.w = fmaxf(acc[li][7] + bs[7], 0.f);
        reinterpret_cast<float4*>(yp)[0] = v0;
        reinterpret_cast<float4*>(yp)[1] = v1;
    }
}

// ---------------------------------------------------------------------------
// LayerNorm over last dim (D=384). One warp per row.
// ---------------------------------------------------------------------------
__global__ __launch_bounds__(256) void ln_kernel(
    const float* __restrict__ x, const float* __restrict__ g,
    const float* __restrict__ beta, float* __restrict__ y)
{
    int row  = blockIdx.x * 8 + (threadIdx.x >> 5);
    int lane = threadIdx.x & 31;
    const float* xr = x + (size_t)row * DD;

    float v[12];
    float s = 0.f, s2 = 0.f;
#pragma unroll
    for (int i = 0; i < 12; i++) {
        v[i] = xr[lane + i * 32];
        s  += v[i];
        s2 += v[i] * v[i];
    }
#pragma unroll
    for (int o = 16; o; o >>= 1) {
        s  += __shfl_xor_sync(0xffffffffu, s, o);
        s2 += __shfl_xor_sync(0xffffffffu, s2, o);
    }
    const float inv = 1.f / (float)DD;
    float mu  = s * inv;
    float var = s2 * inv - mu * mu;
    float rs  = rsqrtf(var + 1e-5f);

    float* yr = y + (size_t)row * DD;
#pragma unroll
    for (int i = 0; i < 12; i++) {
        int c = lane + i * 32;
        yr[c] = (v[i] - mu) * rs * g[c] + beta[c];
    }
}

// ---------------------------------------------------------------------------
// Linear head: dur[b,l] = dot(h[b,l,:], w[:,0]) + b. One warp per row.
// ---------------------------------------------------------------------------
__global__ __launch_bounds__(256) void lin_kernel(
    const float* __restrict__ h, const float* __restrict__ w,
    const float* __restrict__ bias, float* __restrict__ dur_out)
{
    int row  = blockIdx.x * 8 + (threadIdx.x >> 5);
    int lane = threadIdx.x & 31;
    const float* hr = h + (size_t)row * DD;
    float s = 0.f;
#pragma unroll
    for (int i = 0; i < 12; i++) {
        int c = lane + i * 32;
        s = fmaf(hr[c], w[c], s);
    }
#pragma unroll
    for (int o = 16; o; o >>= 1) s += __shfl_xor_sync(0xffffffffu, s, o);
    if (lane == 0) dur_out[row] = s + bias[0];
}

// ---------------------------------------------------------------------------
// Dead-simple serial inclusive prefix scan: one thread per batch.
// L=512 int adds per thread — trivially correct, ~2us.
// ---------------------------------------------------------------------------
__global__ void serial_scan_kernel(const int* __restrict__ dur,
                                   int* __restrict__ cum,
                                   int* __restrict__ total)
{
    int b = threadIdx.x;
    if (b >= BB) return;
    int acc = 0;
    const int* dr = dur + b * LL;
    int* cr = cum + b * LL;
    for (int l = 0; l < LL; l++) {
        acc += dr[l];
        cr[l] = acc;
    }
    total[b] = acc;
}

// ---------------------------------------------------------------------------
// Length regulator as a direct scatter: one block per phoneme (l, b).
// Writes x[b,l,:] to out[b,t,:] for t in [cum[l-1], cum[l]).
// This is definitionally the one-hot alignment einsum:
//   frame t belongs to phoneme j iff cum[j-1] <= t < cum[j];
//   zero-duration phonemes produce no frames (start == end).
// Every t < total[b] is covered exactly once.
// ---------------------------------------------------------------------------
__global__ __launch_bounds__(128) void scatter_kernel(
    const float* __restrict__ x, const int* __restrict__ cum,
    float* __restrict__ out, int T)
{
    int l = blockIdx.x;
    int b = blockIdx.y;
    int lane = threadIdx.x;

    int end   = cum[b * LL + l];
    int start = (l == 0) ? 0 : cum[b * LL + l - 1];
    if (start == end) return;

    const float* xr = x + ((size_t)(b * LL + l)) * DD;
    float r0 = xr[lane];
    float r1 = xr[lane + 128];
    float r2 = xr[lane + 256];

    for (int t = start; t < end; t++) {
        float* o = out + ((size_t)b * T + t) * DD;
        o[lane]       = r0;
        o[lane + 128] = r1;
        o[lane + 256] = r2;
    }
}

// ---------------------------------------------------------------------------
// Zero the padded tail: out[b,t,:] = 0 for t >= total[b].
// Disjoint from scatter region.
// ---------------------------------------------------------------------------
__global__ __launch_bounds__(128) void zero_tail_kernel(
    const int* __restrict__ total, float* __restrict__ out, int T)
{
    int t = blockIdx.x;
    int b = blockIdx.y;
    if (t < total[b]) return;
    int lane = threadIdx.x;
    float* o = out + ((size_t)b * T + t) * DD;
    o[lane]       = 0.f;
    o[lane + 128] = 0.f;
    o[lane + 256] = 0.f;
}

// ---------------------------------------------------------------------------
extern "C" void kernel_launch(void* const* d_in, const int* in_sizes, int n_in,
                              void* d_out, int out_size)
{
    const float* x     = (const float*)d_in[0];
    const int*   dur   = (const int*)  d_in[1];
    const float* c1a_w = (const float*)d_in[2];
    const float* c1a_b = (const float*)d_in[3];
    const float* c1b_w = (const float*)d_in[4];
    const float* c1b_b = (const float*)d_in[5];
    const float* ln1_g = (const float*)d_in[6];
    const float* ln1_b = (const float*)d_in[7];
    const float* c2a_w = (const float*)d_in[8];
    const float* c2a_b = (const float*)d_in[9];
    const float* c2b_w = (const float*)d_in[10];
    const float* c2b_b = (const float*)d_in[11];
    const float* ln2_g = (const float*)d_in[12];
    const float* ln2_b = (const float*)d_in[13];
    const float* lin_w = (const float*)d_in[14];
    const float* lin_b = (const float*)d_in[15];
    float* out = (float*)d_out;

    // out_size = B*T*D + B*L  ->  T
    long T = ((long)out_size - (long)BB * LL) / ((long)BB * DD);

    float *buf0, *buf1;
    int *cum, *total;
    cudaGetSymbolAddress((void**)&buf0,  g_buf0);
    cudaGetSymbolAddress((void**)&buf1,  g_buf1);
    cudaGetSymbolAddress((void**)&cum,   g_cum);
    cudaGetSymbolAddress((void**)&total, g_total);

    dim3 cgrid(LL / BL, DD / BCO, BB);   // (8, 3, 32)

    // Duration predictor
    conv_relu_kernel<<<cgrid, NTHREADS>>>(x,    c1a_w, c1a_b, buf0);
    conv_relu_kernel<<<cgrid, NTHREADS>>>(buf0, c1b_w, c1b_b, buf1);
    ln_kernel<<<BB * LL / 8, 256>>>(buf1, ln1_g, ln1_b, buf0);
    conv_relu_kernel<<<cgrid, NTHREADS>>>(buf0, c2a_w, c2a_b, buf1);
    conv_relu_kernel<<<cgrid, NTHREADS>>>(buf1, c2b_w, c2b_b, buf0);
    ln_kernel<<<BB * LL / 8, 256>>>(buf0, ln2_g, ln2_b, buf1);
    lin_kernel<<<BB * LL / 8, 256>>>(buf1, lin_w, lin_b,
                                     out + (size_t)BB * T * DD);

    // Length regulator
    serial_scan_kernel<<<1, BB>>>(dur, cum, total);
    zero_tail_kernel<<<dim3((unsigned)T, BB), 128>>>(total, out, (int)T);
    scatter_kernel<<<dim3(LL, BB), 128>>>(x, cum, out, (int)T);
}

// round 3
// speedup vs baseline: 1.5941x; 1.5941x over previous
#include <cuda_runtime.h>
#include <cuda_bf16.h>
#include <cstdint>

// Problem constants
#define BB 32
#define LL 512
#define DD 384
#define KK 3

// Conv tiling
#define BL 64      // L rows per block
#define BCO 128    // c_out per block
#define BK 16      // c_in chunk
#define CT 128     // threads per conv block

// Ping-pong intermediates + transposed weights (allocation-free scratch)
__device__ float g_buf0[BB * LL * DD];
__device__ float g_buf1[BB * LL * DD];
__device__ float g_wt[4][DD * KK * DD];   // [ci][k][co] per conv layer
__device__ int   g_cum[BB * LL];
__device__ int   g_total[BB];

// ---- packed fp32 helpers (Blackwell FFMA2) --------------------------------
__device__ __forceinline__ void fma2(unsigned long long& d,
                                     unsigned long long a,
                                     unsigned long long b) {
    asm("fma.rn.f32x2 %0, %1, %2, %0;" : "+l"(d) : "l"(a), "l"(b));
}
__device__ __forceinline__ unsigned long long dup2(float x) {
    unsigned long long r;
    asm("mov.b64 %0, {%1, %1};" : "=l"(r) : "f"(x));
    return r;
}
__device__ __forceinline__ void unpack2(unsigned long long v, float& lo, float& hi) {
    asm("mov.b64 {%0, %1}, %2;" : "=f"(lo), "=f"(hi) : "l"(v));
}

// ---------------------------------------------------------------------------
// Weight transpose: w[co][ci][k] -> wt[ci][k][co]   (per conv layer)
// ---------------------------------------------------------------------------
__global__ void wtrans_kernel(const float* __restrict__ w, float* __restrict__ wt)
{
    int idx = blockIdx.x * blockDim.x + threadIdx.x;   // over DD*DD*KK
    if (idx >= DD * DD * KK) return;
    int co = idx / (DD * KK);
    int r  = idx - co * (DD * KK);
    int ci = r / KK;
    int k  = r - ci * KK;
    wt[(ci * KK + k) * DD + co] = w[idx];
}

// ---------------------------------------------------------------------------
// Conv1D (K=3, SAME) + bias + ReLU, fp32 via packed f32x2 FMA.
// x: [B, L, D]; wt: [ci][k][co]; y: [B, L, D]
// Block: 64 L-rows x 128 c_out, 128 threads, thread tile 8L x 8co.
// Cols per thread: group0 = tc*4 + {0..3}, group1 = 64 + tc*4 + {0..3}.
// ---------------------------------------------------------------------------
__global__ __launch_bounds__(CT, 4) void conv_f32x2_kernel(
    const float* __restrict__ x, const float* __restrict__ wt,
    const float* __restrict__ bias, float* __restrict__ y)
{
    __shared__ float As[BK][76];            // [ci][row 0..65 halo], pad->76 (16B aligned)
    __shared__ float Ws[BK][KK][BCO];       // [ci][k][co]

    const int b   = blockIdx.z;
    const int l0  = blockIdx.x * BL;
    const int co0 = blockIdx.y * BCO;
    const int tid = threadIdx.x;
    const int tc  = tid & 15;               // col group
    const int tr  = tid >> 4;               // 0..7 row group
    const int lr  = tr * 8;

    unsigned long long acc[8][4];
#pragma unroll
    for (int i = 0; i < 8; i++)
#pragma unroll
        for (int j = 0; j < 4; j++) acc[i][j] = 0ull;

    for (int k0 = 0; k0 < DD; k0 += BK) {
        // ---- x tile with halo: As[ci][r], r = l - l0 + 1, r in [0,65] ----
        for (int idx = tid; idx < 66 * 4; idx += CT) {
            int r = idx >> 2;               // 0..65
            int g = idx & 3;                // ci group of 4
            int l = l0 - 1 + r;
            float4 v = make_float4(0.f, 0.f, 0.f, 0.f);
            if (l >= 0 && l < LL)
                v = *reinterpret_cast<const float4*>(
                        &x[((size_t)(b * LL + l)) * DD + k0 + g * 4]);
            As[g * 4 + 0][r] = v.x;
            As[g * 4 + 1][r] = v.y;
            As[g * 4 + 2][r] = v.z;
            As[g * 4 + 3][r] = v.w;
        }
        // ---- weights: coalesced + conflict-free (co fastest both sides) ----
        for (int idx = tid; idx < BK * KK * BCO; idx += CT) {
            int co = idx & (BCO - 1);
            int q  = idx >> 7;              // ci*3 + k, 0..47
            int ci = q / 3;
            int k  = q - ci * 3;
            Ws[ci][k][co] = wt[((k0 + ci) * KK + k) * DD + co0 + co];
        }
        __syncthreads();

#pragma unroll 2
        for (int ci = 0; ci < BK; ci++) {
            // A window rows lr..lr+9 (broadcast loads)
            const float* ap = &As[ci][lr];
            float4 x0 = *reinterpret_cast<const float4*>(ap);
            float4 x1 = *reinterpret_cast<const float4*>(ap + 4);
            float4 x2 = *reinterpret_cast<const float4*>(ap + 8);
            unsigned long long ad[10];
            ad[0] = dup2(x0.x); ad[1] = dup2(x0.y); ad[2] = dup2(x0.z); ad[3] = dup2(x0.w);
            ad[4] = dup2(x1.x); ad[5] = dup2(x1.y); ad[6] = dup2(x1.z); ad[7] = dup2(x1.w);
            ad[8] = dup2(x2.x); ad[9] = dup2(x2.y);

#pragma unroll
            for (int k = 0; k < KK; k++) {
                // weight pairs come free from LDS.128 halves
                ulonglong2 wa = *reinterpret_cast<const ulonglong2*>(&Ws[ci][k][tc * 4]);
                ulonglong2 wb = *reinterpret_cast<const ulonglong2*>(&Ws[ci][k][64 + tc * 4]);
#pragma unroll
                for (int li = 0; li < 8; li++) {
                    fma2(acc[li][0], ad[li + k], wa.x);
                    fma2(acc[li][1], ad[li + k], wa.y);
                    fma2(acc[li][2], ad[li + k], wb.x);
                    fma2(acc[li][3], ad[li + k], wb.y);
                }
            }
        }
        __syncthreads();
    }

    // ---- epilogue: bias + ReLU ----
    float b0[4], b1[4];
#pragma unroll
    for (int j = 0; j < 4; j++) {
        b0[j] = bias[co0 + tc * 4 + j];
        b1[j] = bias[co0 + 64 + tc * 4 + j];
    }
#pragma unroll
    for (int li = 0; li < 8; li++) {
        int l = l0 + lr + li;
        float* yp = &y[((size_t)(b * LL + l)) * DD + co0];
        float4 v0, v1;
        unpack2(acc[li][0], v0.x, v0.y);
        unpack2(acc[li][1], v0.z, v0.w);
        unpack2(acc[li][2], v1.x, v1.y);
        unpack2(acc[li][3], v1.z, v1.w);
        v0.x = fmaxf(v0.x + b0[0], 0.f); v0.y = fmaxf(v0.y + b0[1], 0.f);
        v0.z = fmaxf(v0.z + b0[2], 0.f); v0.w = fmaxf(v0.w + b0[3], 0.f);
        v1.x = fmaxf(v1.x + b1[0], 0.f); v1.y = fmaxf(v1.y + b1[1], 0.f);
        v1.z = fmaxf(v1.z + b1[2], 0.f); v1.w = fmaxf(v1.w + b1[3], 0.f);
        *reinterpret_cast<float4*>(yp + tc * 4)      = v0;
        *reinterpret_cast<float4*>(yp + 64 + tc * 4) = v1;
    }
}

// ---------------------------------------------------------------------------
// LayerNorm over last dim (D=384). One warp per row.
// ---------------------------------------------------------------------------
__global__ __launch_bounds__(256) void ln_kernel(
    const float* __restrict__ x, const float* __restrict__ g,
    const float* __restrict__ beta, float* __restrict__ y)
{
    int row  = blockIdx.x * 8 + (threadIdx.x >> 5);
    int lane = threadIdx.x & 31;
    const float* xr = x + (size_t)row * DD;

    float v[12];
    float s = 0.f, s2 = 0.f;
#pragma unroll
    for (int i = 0; i < 12; i++) {
        v[i] = xr[lane + i * 32];
        s  += v[i];
        s2 += v[i] * v[i];
    }
#pragma unroll
    for (int o = 16; o; o >>= 1) {
        s  += __shfl_xor_sync(0xffffffffu, s, o);
        s2 += __shfl_xor_sync(0xffffffffu, s2, o);
    }
    const float inv = 1.f / (float)DD;
    float mu  = s * inv;
    float var = s2 * inv - mu * mu;
    float rs  = rsqrtf(var + 1e-5f);

    float* yr = y + (size_t)row * DD;
#pragma unroll
    for (int i = 0; i < 12; i++) {
        int c = lane + i * 32;
        yr[c] = (v[i] - mu) * rs * g[c] + beta[c];
    }
}

// ---------------------------------------------------------------------------
// Linear head: dur[b,l] = dot(h[b,l,:], w[:,0]) + b. One warp per row.
// ---------------------------------------------------------------------------
__global__ __launch_bounds__(256) void lin_kernel(
    const float* __restrict__ h, const float* __restrict__ w,
    const float* __restrict__ bias, float* __restrict__ dur_out)
{
    int row  = blockIdx.x * 8 + (threadIdx.x >> 5);
    int lane = threadIdx.x & 31;
    const float* hr = h + (size_t)row * DD;
    float s = 0.f;
#pragma unroll
    for (int i = 0; i < 12; i++) {
        int c = lane + i * 32;
        s = fmaf(hr[c], w[c], s);
    }
#pragma unroll
    for (int o = 16; o; o >>= 1) s += __shfl_xor_sync(0xffffffffu, s, o);
    if (lane == 0) dur_out[row] = s + bias[0];
}

// ---------------------------------------------------------------------------
// Serial inclusive prefix scan: one thread per batch (trivially correct).
// ---------------------------------------------------------------------------
__global__ void serial_scan_kernel(const int* __restrict__ dur,
                                   int* __restrict__ cum,
                                   int* __restrict__ total)
{
    int b = threadIdx.x;
    if (b >= BB) return;
    int acc = 0;
    const int* dr = dur + b * LL;
    int* cr = cum + b * LL;
    for (int l = 0; l < LL; l++) {
        acc += dr[l];
        cr[l] = acc;
    }
    total[b] = acc;
}

// ---------------------------------------------------------------------------
// Length regulator scatter: block per phoneme (l, b); frames [cum[l-1],cum[l]).
// ---------------------------------------------------------------------------
__global__ __launch_bounds__(128) void scatter_kernel(
    const float* __restrict__ x, const int* __restrict__ cum,
    float* __restrict__ out, int T)
{
    int l = blockIdx.x;
    int b = blockIdx.y;
    int lane = threadIdx.x;

    int end   = cum[b * LL + l];
    int start = (l == 0) ? 0 : cum[b * LL + l - 1];
    if (start == end) return;

    const float* xr = x + ((size_t)(b * LL + l)) * DD;
    float r0 = xr[lane];
    float r1 = xr[lane + 128];
    float r2 = xr[lane + 256];

    for (int t = start; t < end; t++) {
        float* o = out + ((size_t)b * T + t) * DD;
        o[lane]       = r0;
        o[lane + 128] = r1;
        o[lane + 256] = r2;
    }
}

// ---------------------------------------------------------------------------
// Zero the padded tail: out[b,t,:] = 0 for t >= total[b].
// ---------------------------------------------------------------------------
__global__ __launch_bounds__(128) void zero_tail_kernel(
    const int* __restrict__ total, float* __restrict__ out, int T)
{
    int t = blockIdx.x;
    int b = blockIdx.y;
    if (t < total[b]) return;
    int lane = threadIdx.x;
    float* o = out + ((size_t)b * T + t) * DD;
    o[lane]       = 0.f;
    o[lane + 128] = 0.f;
    o[lane + 256] = 0.f;
}

// ---------------------------------------------------------------------------
extern "C" void kernel_launch(void* const* d_in, const int* in_sizes, int n_in,
                              void* d_out, int out_size)
{
    const float* x     = (const float*)d_in[0];
    const int*   dur   = (const int*)  d_in[1];
    const float* c1a_w = (const float*)d_in[2];
    const float* c1a_b = (const float*)d_in[3];
    const float* c1b_w = (const float*)d_in[4];
    const float* c1b_b = (const float*)d_in[5];
    const float* ln1_g = (const float*)d_in[6];
    const float* ln1_b = (const float*)d_in[7];
    const float* c2a_w = (const float*)d_in[8];
    const float* c2a_b = (const float*)d_in[9];
    const float* c2b_w = (const float*)d_in[10];
    const float* c2b_b = (const float*)d_in[11];
    const float* ln2_g = (const float*)d_in[12];
    const float* ln2_b = (const float*)d_in[13];
    const float* lin_w = (const float*)d_in[14];
    const float* lin_b = (const float*)d_in[15];
    float* out = (float*)d_out;

    // out_size = B*T*D + B*L  ->  T
    long T = ((long)out_size - (long)BB * LL) / ((long)BB * DD);

    float *buf0, *buf1, *wt;
    int *cum, *total;
    cudaGetSymbolAddress((void**)&buf0,  g_buf0);
    cudaGetSymbolAddress((void**)&buf1,  g_buf1);
    cudaGetSymbolAddress((void**)&wt,    g_wt);
    cudaGetSymbolAddress((void**)&cum,   g_cum);
    cudaGetSymbolAddress((void**)&total, g_total);

    const int WN = DD * DD * KK;           // elems per weight tensor
    float* wt0 = wt;
    float* wt1 = wt + WN;
    float* wt2 = wt + 2 * WN;
    float* wt3 = wt + 3 * WN;

    int wtb = (WN + 255) / 256;
    wtrans_kernel<<<wtb, 256>>>(c1a_w, wt0);
    wtrans_kernel<<<wtb, 256>>>(c1b_w, wt1);
    wtrans_kernel<<<wtb, 256>>>(c2a_w, wt2);
    wtrans_kernel<<<wtb, 256>>>(c2b_w, wt3);

    dim3 cgrid(LL / BL, DD / BCO, BB);     // (8, 3, 32)

    // Duration predictor
    conv_f32x2_kernel<<<cgrid, CT>>>(x,    wt0, c1a_b, buf0);
    conv_f32x2_kernel<<<cgrid, CT>>>(buf0, wt1, c1b_b, buf1);
    ln_kernel<<<BB * LL / 8, 256>>>(buf1, ln1_g, ln1_b, buf0);
    conv_f32x2_kernel<<<cgrid, CT>>>(buf0, wt2, c2a_b, buf1);
    conv_f32x2_kernel<<<cgrid, CT>>>(buf1, wt3, c2b_b, buf0);
    ln_kernel<<<BB * LL / 8, 256>>>(buf0, ln2_g, ln2_b, buf1);
    lin_kernel<<<BB * LL / 8, 256>>>(buf1, lin_w, lin_b,
                                     out + (size_t)BB * T * DD);

    // Length regulator
    serial_scan_kernel<<<1, BB>>>(dur, cum, total);
    zero_tail_kernel<<<dim3((unsigned)T, BB), 128>>>(total, out, (int)T);
    scatter_kernel<<<dim3(LL, BB), 128>>>(x, cum, out, (int)T);
}

// round 5
// speedup vs baseline: 2.5726x; 1.6138x over previous
#include <cuda_runtime.h>
#include <cuda_bf16.h>
#include <cstdint>

// Problem constants
#define BB 32
#define LL 512
#define DD 384
#define KK 3
#define KTOT (DD * KK)        // 1152 GEMM-K
#define NROWS (BB * LL)       // 16384 GEMM-M

// Conv MMA tiling
#define MT 128                // M rows per CTA (L-tile)
#define NT 128                // N cols per CTA (c_out tile)
#define KC 64                 // K chunk (one tap segment slice)
#define NCHUNK (KTOT / KC)    // 18
#define CTT 256               // 8 warps
#define SP 72                 // smem row stride in halves (144B, conflict-free)

// smem offsets (bytes): 4 tiles of 128 x 72 halves = 18432B each
#define SM_AH 0
#define SM_AL 18432
#define SM_BH 36864
#define SM_BL 55296
#define SM_TOT 73728

// ---------------- device scratch (allocation-free) -------------------------
__device__ float g_y0[NROWS * DD];
__device__ float g_y1[NROWS * DD];
__device__ __align__(16) __nv_bfloat16 g_ah[NROWS * DD];
__device__ __align__(16) __nv_bfloat16 g_al[NROWS * DD];
__device__ __align__(16) __nv_bfloat16 g_bh[NROWS * DD];
__device__ __align__(16) __nv_bfloat16 g_bl[NROWS * DD];
__device__ __align__(16) __nv_bfloat16 g_wh[4][DD * KTOT];  // [co][k*384+ci]
__device__ __align__(16) __nv_bfloat16 g_wl[4][DD * KTOT];
__device__ int g_cum[BB * LL];
__device__ int g_total[BB];

// ---------------- helpers --------------------------------------------------
__device__ __forceinline__ void bsplit(float v, __nv_bfloat16& h, __nv_bfloat16& l) {
    h = __float2bfloat16_rn(v);
    l = __float2bfloat16_rn(v - __bfloat162float(h));
}

#define MMA_BF16(c, a0, a1, a2, a3, b0, b1)                                    \
    asm volatile(                                                              \
        "mma.sync.aligned.m16n8k16.row.col.f32.bf16.bf16.f32 "                 \
        "{%0,%1,%2,%3},{%4,%5,%6,%7},{%8,%9},{%0,%1,%2,%3};"                   \
        : "+f"((c)[0]), "+f"((c)[1]), "+f"((c)[2]), "+f"((c)[3])               \
        : "r"(a0), "r"(a1), "r"(a2), "r"(a3), "r"(b0), "r"(b1))

// ---------------------------------------------------------------------------
// Conv1D(K=3,SAME)+bias+ReLU as HMMA bf16 GEMM with 3-term bf16 splitting.
// ah/al: bf16 hi/lo of input [NROWS,384]; wh/wl: [384 co][1152 kappa], kappa=k*384+ci.
// Optional outputs: y fp32, oh/ol bf16 split of relu(result).
// Grid (4 Lt, 3 Nt, 32 b), 256 threads.
// ---------------------------------------------------------------------------
__global__ __launch_bounds__(CTT, 1) void conv_mma_kernel(
    const __nv_bfloat16* __restrict__ ah, const __nv_bfloat16* __restrict__ al,
    const __nv_bfloat16* __restrict__ wh, const __nv_bfloat16* __restrict__ wl,
    const float* __restrict__ bias,
    float* __restrict__ y,
    __nv_bfloat16* __restrict__ oh, __nv_bfloat16* __restrict__ ol)
{
    extern __shared__ char smem[];
    const int tid  = threadIdx.x;
    const int wid  = tid >> 5;
    const int lane = tid & 31;
    const int g    = lane >> 2;         // 0..7
    const int tg   = lane & 3;          // 0..3
    const int b    = blockIdx.z;
    const int l0   = blockIdx.x * MT;
    const int co0  = blockIdx.y * NT;
    const int mBase = (wid & 3) * 32;   // warp M offset
    const int nBase = (wid >> 2) * 64;  // warp N offset

    uint32_t* Ah32 = reinterpret_cast<uint32_t*>(smem + SM_AH);
    uint32_t* Al32 = reinterpret_cast<uint32_t*>(smem + SM_AL);
    uint32_t* Bh32 = reinterpret_cast<uint32_t*>(smem + SM_BH);
    uint32_t* Bl32 = reinterpret_cast<uint32_t*>(smem + SM_BL);

    float acc[2][8][4];
#pragma unroll
    for (int mf = 0; mf < 2; mf++)
#pragma unroll
        for (int nf = 0; nf < 8; nf++)
#pragma unroll
            for (int q = 0; q < 4; q++) acc[mf][nf][q] = 0.f;

    for (int c = 0; c < NCHUNK; c++) {
        const int kappa0 = c * KC;
        const int seg = kappa0 / DD;        // conv tap 0..2
        const int ci0 = kappa0 - seg * DD;  // input-channel base

        // ---- stage A tiles (shifted rows) ----
        for (int idx = tid; idx < MT * 8; idx += CTT) {
            const int r = idx >> 3, gg = idx & 7;
            const int l = l0 + r + seg - 1;
            uint4 vh = make_uint4(0, 0, 0, 0), vl = vh;
            if ((unsigned)l < LL) {
                const size_t go = ((size_t)(b * LL + l)) * DD + ci0 + gg * 8;
                vh = *reinterpret_cast<const uint4*>(ah + go);
                vl = *reinterpret_cast<const uint4*>(al + go);
            }
            *reinterpret_cast<uint4*>(smem + SM_AH + r * 144 + gg * 16) = vh;
            *reinterpret_cast<uint4*>(smem + SM_AL + r * 144 + gg * 16) = vl;
        }
        // ---- stage B tiles ----
        for (int idx = tid; idx < NT * 8; idx += CTT) {
            const int r = idx >> 3, gg = idx & 7;
            const size_t go = (size_t)(co0 + r) * KTOT + kappa0 + gg * 8;
            *reinterpret_cast<uint4*>(smem + SM_BH + r * 144 + gg * 16) =
                *reinterpret_cast<const uint4*>(wh + go);
            *reinterpret_cast<uint4*>(smem + SM_BL + r * 144 + gg * 16) =
                *reinterpret_cast<const uint4*>(wl + go);
        }
        __syncthreads();

#pragma unroll
        for (int kk = 0; kk < 4; kk++) {            // K=16 steps in chunk
            const int kw = kk * 8 + tg;             // word offset in row
            uint32_t bh[8][2], bl[8][2];
#pragma unroll
            for (int nf = 0; nf < 8; nf++) {
                const int off = (nBase + nf * 8 + g) * 36 + kw;
                bh[nf][0] = Bh32[off];
                bh[nf][1] = Bh32[off + 4];
                bl[nf][0] = Bl32[off];
                bl[nf][1] = Bl32[off + 4];
            }
#pragma unroll
            for (int mf = 0; mf < 2; mf++) {
                const int m = mBase + mf * 16 + g;
                const int off  = m * 36 + kw;
                const int off8 = off + 8 * 36;
                const uint32_t ah0 = Ah32[off],     ah1 = Ah32[off8];
                const uint32_t ah2 = Ah32[off + 4], ah3 = Ah32[off8 + 4];
                const uint32_t al0 = Al32[off],     al1 = Al32[off8];
                const uint32_t al2 = Al32[off + 4], al3 = Al32[off8 + 4];
#pragma unroll
                for (int nf = 0; nf < 8; nf++) {
                    MMA_BF16(acc[mf][nf], ah0, ah1, ah2, ah3, bh[nf][0], bh[nf][1]);
                    MMA_BF16(acc[mf][nf], ah0, ah1, ah2, ah3, bl[nf][0], bl[nf][1]);
                    MMA_BF16(acc[mf][nf], al0, al1, al2, al3, bh[nf][0], bh[nf][1]);
                }
            }
        }
        __syncthreads();
    }

    // ---- epilogue: bias + ReLU; optional fp32 / bf16-split stores ----
#pragma unroll
    for (int mf = 0; mf < 2; mf++) {
        const int m0 = mBase + mf * 16 + g;
        const size_t grow0 = ((size_t)(b * LL + l0 + m0)) * DD;
        const size_t grow1 = ((size_t)(b * LL + l0 + m0 + 8)) * DD;
#pragma unroll
        for (int nf = 0; nf < 8; nf++) {
            const int n0 = co0 + nBase + nf * 8 + tg * 2;
            const float bi0 = __ldg(bias + n0);
            const float bi1 = __ldg(bias + n0 + 1);
            float v0 = fmaxf(acc[mf][nf][0] + bi0, 0.f);
            float v1 = fmaxf(acc[mf][nf][1] + bi1, 0.f);
            float v2 = fmaxf(acc[mf][nf][2] + bi0, 0.f);
            float v3 = fmaxf(acc[mf][nf][3] + bi1, 0.f);
            if (y) {
                *reinterpret_cast<float2*>(y + grow0 + n0) = make_float2(v0, v1);
                *reinterpret_cast<float2*>(y + grow1 + n0) = make_float2(v2, v3);
            }
            if (oh) {
                __nv_bfloat16 h0, l0b, h1, l1, h2, l2, h3, l3;
                bsplit(v0, h0, l0b); bsplit(v1, h1, l1);
                bsplit(v2, h2, l2);  bsplit(v3, h3, l3);
                uint32_t hw0 = (uint32_t)__bfloat16_as_ushort(h0) |
                               ((uint32_t)__bfloat16_as_ushort(h1) << 16);
                uint32_t lw0 = (uint32_t)__bfloat16_as_ushort(l0b) |
                               ((uint32_t)__bfloat16_as_ushort(l1) << 16);
                uint32_t hw1 = (uint32_t)__bfloat16_as_ushort(h2) |
                               ((uint32_t)__bfloat16_as_ushort(h3) << 16);
                uint32_t lw1 = (uint32_t)__bfloat16_as_ushort(l2) |
                               ((uint32_t)__bfloat16_as_ushort(l3) << 16);
                *reinterpret_cast<uint32_t*>(oh + grow0 + n0) = hw0;
                *reinterpret_cast<uint32_t*>(ol + grow0 + n0) = lw0;
                *reinterpret_cast<uint32_t*>(oh + grow1 + n0) = hw1;
                *reinterpret_cast<uint32_t*>(ol + grow1 + n0) = lw1;
            }
        }
    }
}

// ---------------------------------------------------------------------------
// Split fp32 -> bf16 hi/lo (for initial x)
// ---------------------------------------------------------------------------
__global__ void split_kernel(const float* __restrict__ x,
                             __nv_bfloat16* __restrict__ oh,
                             __nv_bfloat16* __restrict__ ol, int n)
{
    int i = blockIdx.x * blockDim.x + threadIdx.x;
    if (i >= n) return;
    __nv_bfloat16 h, l;
    bsplit(x[i], h, l);
    oh[i] = h;
    ol[i] = l;
}

// ---------------------------------------------------------------------------
// Weight prep: w[co][ci][k] fp32 -> wh/wl[co][k*384+ci] bf16
// ---------------------------------------------------------------------------
__global__ void wsplit_kernel(const float* __restrict__ w,
                              __nv_bfloat16* __restrict__ wh,
                              __nv_bfloat16* __restrict__ wl)
{
    int idx = blockIdx.x * blockDim.x + threadIdx.x;
    if (idx >= DD * KTOT) return;
    int co = idx / KTOT;
    int kp = idx - co * KTOT;
    int k  = kp / DD;
    int ci = kp - k * DD;
    __nv_bfloat16 h, l;
    bsplit(w[co * KTOT + ci * KK + k], h, l);
    wh[idx] = h;
    wl[idx] = l;
}

// ---------------------------------------------------------------------------
// LayerNorm (D=384), one warp per row; optional fp32 out + bf16 hi/lo split.
// ---------------------------------------------------------------------------
__global__ __launch_bounds__(256) void ln_kernel(
    const float* __restrict__ x, const float* __restrict__ g,
    const float* __restrict__ beta, float* __restrict__ y,
    __nv_bfloat16* __restrict__ oh, __nv_bfloat16* __restrict__ ol)
{
    int row  = blockIdx.x * 8 + (threadIdx.x >> 5);
    int lane = threadIdx.x & 31;
    const float* xr = x + (size_t)row * DD;

    float v[12];
    float s = 0.f, s2 = 0.f;
#pragma unroll
    for (int i = 0; i < 12; i++) {
        v[i] = xr[lane + i * 32];
        s  += v[i];
        s2 += v[i] * v[i];
    }
#pragma unroll
    for (int o = 16; o; o >>= 1) {
        s  += __shfl_xor_sync(0xffffffffu, s, o);
        s2 += __shfl_xor_sync(0xffffffffu, s2, o);
    }
    const float inv = 1.f / (float)DD;
    float mu  = s * inv;
    float var = s2 * inv - mu * mu;
    float rs  = rsqrtf(var + 1e-5f);

    float* yr = y ? y + (size_t)row * DD : nullptr;
    __nv_bfloat16* hr = oh ? oh + (size_t)row * DD : nullptr;
    __nv_bfloat16* lr = ol ? ol + (size_t)row * DD : nullptr;
#pragma unroll
    for (int i = 0; i < 12; i++) {
        int c = lane + i * 32;
        float o2 = (v[i] - mu) * rs * g[c] + beta[c];
        if (yr) yr[c] = o2;
        if (hr) {
            __nv_bfloat16 h, l;
            bsplit(o2, h, l);
            hr[c] = h;
            lr[c] = l;
        }
    }
}

// ---------------------------------------------------------------------------
// Linear head: dur[row] = dot(h[row,:], w) + b. One warp per row.
// ---------------------------------------------------------------------------
__global__ __launch_bounds__(256) void lin_kernel(
    const float* __restrict__ h, const float* __restrict__ w,
    const float* __restrict__ bias, float* __restrict__ dur_out)
{
    int row  = blockIdx.x * 8 + (threadIdx.x >> 5);
    int lane = threadIdx.x & 31;
    const float* hr = h + (size_t)row * DD;
    float s = 0.f;
#pragma unroll
    for (int i = 0; i < 12; i++) {
        int c = lane + i * 32;
        s = fmaf(hr[c], w[c], s);
    }
#pragma unroll
    for (int o = 16; o; o >>= 1) s += __shfl_xor_sync(0xffffffffu, s, o);
    if (lane == 0) dur_out[row] = s + bias[0];
}

// ---------------------------------------------------------------------------
// Serial inclusive prefix scan: one thread per batch.
// ---------------------------------------------------------------------------
__global__ void serial_scan_kernel(const int* __restrict__ dur,
                                   int* __restrict__ cum,
                                   int* __restrict__ total)
{
    int b = threadIdx.x;
    if (b >= BB) return;
    int acc = 0;
    const int* dr = dur + b * LL;
    int* cr = cum + b * LL;
    for (int l = 0; l < LL; l++) {
        acc += dr[l];
        cr[l] = acc;
    }
    total[b] = acc;
}

// ---------------------------------------------------------------------------
// Length regulator scatter + tail zero (proven correct).
// ---------------------------------------------------------------------------
__global__ __launch_bounds__(128) void scatter_kernel(
    const float* __restrict__ x, const int* __restrict__ cum,
    float* __restrict__ out, int T)
{
    int l = blockIdx.x;
    int b = blockIdx.y;
    int lane = threadIdx.x;

    int end   = cum[b * LL + l];
    int start = (l == 0) ? 0 : cum[b * LL + l - 1];
    if (start == end) return;

    const float* xr = x + ((size_t)(b * LL + l)) * DD;
    float r0 = xr[lane];
    float r1 = xr[lane + 128];
    float r2 = xr[lane + 256];

    for (int t = start; t < end; t++) {
        float* o = out + ((size_t)b * T + t) * DD;
        o[lane]       = r0;
        o[lane + 128] = r1;
        o[lane + 256] = r2;
    }
}

__global__ __launch_bounds__(128) void zero_tail_kernel(
    const int* __restrict__ total, float* __restrict__ out, int T)
{
    int t = blockIdx.x;
    int b = blockIdx.y;
    if (t < total[b]) return;
    int lane = threadIdx.x;
    float* o = out + ((size_t)b * T + t) * DD;
    o[lane]       = 0.f;
    o[lane + 128] = 0.f;
    o[lane + 256] = 0.f;
}

// ---------------------------------------------------------------------------
extern "C" void kernel_launch(void* const* d_in, const int* in_sizes, int n_in,
                              void* d_out, int out_size)
{
    const float* x     = (const float*)d_in[0];
    const int*   dur   = (const int*)  d_in[1];
    const float* c1a_w = (const float*)d_in[2];
    const float* c1a_b = (const float*)d_in[3];
    const float* c1b_w = (const float*)d_in[4];
    const float* c1b_b = (const float*)d_in[5];
    const float* ln1_g = (const float*)d_in[6];
    const float* ln1_b = (const float*)d_in[7];
    const float* c2a_w = (const float*)d_in[8];
    const float* c2a_b = (const float*)d_in[9];
    const float* c2b_w = (const float*)d_in[10];
    const float* c2b_b = (const float*)d_in[11];
    const float* ln2_g = (const float*)d_in[12];
    const float* ln2_b = (const float*)d_in[13];
    const float* lin_w = (const float*)d_in[14];
    const float* lin_b = (const float*)d_in[15];
    float* out = (float*)d_out;

    long T = ((long)out_size - (long)BB * LL) / ((long)BB * DD);

    float *y0, *y1;
    __nv_bfloat16 *ah, *al, *bh, *bl, *wh, *wl;
    int *cum, *total;
    cudaGetSymbolAddress((void**)&y0,    g_y0);
    cudaGetSymbolAddress((void**)&y1,    g_y1);
    cudaGetSymbolAddress((void**)&ah,    g_ah);
    cudaGetSymbolAddress((void**)&al,    g_al);
    cudaGetSymbolAddress((void**)&bh,    g_bh);
    cudaGetSymbolAddress((void**)&bl,    g_bl);
    cudaGetSymbolAddress((void**)&wh,    g_wh);
    cudaGetSymbolAddress((void**)&wl,    g_wl);
    cudaGetSymbolAddress((void**)&cum,   g_cum);
    cudaGetSymbolAddress((void**)&total, g_total);

    cudaFuncSetAttribute(conv_mma_kernel,
                         cudaFuncAttributeMaxDynamicSharedMemorySize, SM_TOT);

    const int WN = DD * KTOT;
    const int n  = NROWS * DD;

    // Prep: operand splits
    split_kernel<<<(n + 255) / 256, 256>>>(x, ah, al, n);
    wsplit_kernel<<<(WN + 255) / 256, 256>>>(c1a_w, wh,          wl);
    wsplit_kernel<<<(WN + 255) / 256, 256>>>(c1b_w, wh + WN,     wl + WN);
    wsplit_kernel<<<(WN + 255) / 256, 256>>>(c2a_w, wh + 2 * WN, wl + 2 * WN);
    wsplit_kernel<<<(WN + 255) / 256, 256>>>(c2b_w, wh + 3 * WN, wl + 3 * WN);

    dim3 cgrid(LL / MT, DD / NT, BB);   // (4, 3, 32)

    // Duration predictor (HMMA tensor-core convs)
    conv_mma_kernel<<<cgrid, CTT, SM_TOT>>>(ah, al, wh,          wl,          c1a_b,
                                            nullptr, bh, bl);
    conv_mma_kernel<<<cgrid, CTT, SM_TOT>>>(bh, bl, wh + WN,     wl + WN,     c1b_b,
                                            y0, nullptr, nullptr);
    ln_kernel<<<NROWS / 8, 256>>>(y0, ln1_g, ln1_b, nullptr, ah, al);
    conv_mma_kernel<<<cgrid, CTT, SM_TOT>>>(ah, al, wh + 2 * WN, wl + 2 * WN, c2a_b,
                                            nullptr, bh, bl);
    conv_mma_kernel<<<cgrid, CTT, SM_TOT>>>(bh, bl, wh + 3 * WN, wl + 3 * WN, c2b_b,
                                            y0, nullptr, nullptr);
    ln_kernel<<<NROWS / 8, 256>>>(y0, ln2_g, ln2_b, y1, nullptr, nullptr);
    lin_kernel<<<NROWS / 8, 256>>>(y1, lin_w, lin_b, out + (size_t)BB * T * DD);

    // Length regulator
    serial_scan_kernel<<<1, BB>>>(dur, cum, total);
    zero_tail_kernel<<<dim3((unsigned)T, BB), 128>>>(total, out, (int)T);
    scatter_kernel<<<dim3(LL, BB), 128>>>(x, cum, out, (int)T);
}

// round 6
// speedup vs baseline: 3.8301x; 1.4888x over previous
#include <cuda_runtime.h>
#include <cuda_bf16.h>
#include <cstdint>

// Problem constants
#define BB 32
#define LL 512
#define DD 384
#define KK 3
#define KTOT (DD * KK)        // 1152 GEMM-K
#define NROWS (BB * LL)       // 16384 GEMM-M

// Conv MMA tiling
#define MT 128                // M rows per CTA (L-tile)
#define NT 128                // N cols per CTA (c_out tile)
#define KC 64                 // K chunk (one tap segment slice)
#define NCHUNK (KTOT / KC)    // 18
#define CTT 256               // 8 warps

// smem: per stage, 4 tiles of 128 rows x 72 halves (144B row) = 18432B each
#define TILE_B 18432
#define SM_AH 0
#define SM_AL TILE_B
#define SM_BH (2 * TILE_B)
#define SM_BL (3 * TILE_B)
#define STAGE_B (4 * TILE_B)          // 73728
#define SM_TOT (2 * STAGE_B)          // 147456

// ---------------- device scratch (allocation-free) -------------------------
__device__ float g_y0[NROWS * DD];
__device__ float g_y1[NROWS * DD];
__device__ __align__(16) __nv_bfloat16 g_ah[NROWS * DD];
__device__ __align__(16) __nv_bfloat16 g_al[NROWS * DD];
__device__ __align__(16) __nv_bfloat16 g_bh[NROWS * DD];
__device__ __align__(16) __nv_bfloat16 g_bl[NROWS * DD];
__device__ __align__(16) __nv_bfloat16 g_wh[4][DD * KTOT];  // [co][k*384+ci]
__device__ __align__(16) __nv_bfloat16 g_wl[4][DD * KTOT];
__device__ int g_cum[BB * LL];
__device__ int g_total[BB];

// ---------------- helpers --------------------------------------------------
__device__ __forceinline__ void bsplit(float v, __nv_bfloat16& h, __nv_bfloat16& l) {
    h = __float2bfloat16_rn(v);
    l = __float2bfloat16_rn(v - __bfloat162float(h));
}
__device__ __forceinline__ uint32_t smem_u32(const void* p) {
    uint32_t a;
    asm("{ .reg .u64 t; cvta.to.shared.u64 t, %1; cvt.u32.u64 %0, t; }"
        : "=r"(a) : "l"(p));
    return a;
}

#define CP16(dst, src, sz)                                                     \
    asm volatile("cp.async.cg.shared.global [%0], [%1], 16, %2;"               \
                 :: "r"(dst), "l"(src), "r"(sz) : "memory")
#define CP_COMMIT()  asm volatile("cp.async.commit_group;" ::: "memory")
#define CP_WAIT(n)   asm volatile("cp.async.wait_group %0;" :: "n"(n) : "memory")

#define MMA_BF16(c, a0, a1, a2, a3, b0, b1)                                    \
    asm volatile(                                                              \
        "mma.sync.aligned.m16n8k16.row.col.f32.bf16.bf16.f32 "                 \
        "{%0,%1,%2,%3},{%4,%5,%6,%7},{%8,%9},{%0,%1,%2,%3};"                   \
        : "+f"((c)[0]), "+f"((c)[1]), "+f"((c)[2]), "+f"((c)[3])               \
        : "r"(a0), "r"(a1), "r"(a2), "r"(a3), "r"(b0), "r"(b1))

// ---------------------------------------------------------------------------
// Conv1D(K=3,SAME)+bias+ReLU as HMMA bf16 GEMM with 3-term bf16 splitting.
// 2-stage cp.async pipeline over 18 K-chunks.
// Grid (4 Lt, 3 Nt, 32 b), 256 threads.
// ---------------------------------------------------------------------------
__global__ __launch_bounds__(CTT, 1) void conv_mma_kernel(
    const __nv_bfloat16* __restrict__ ah, const __nv_bfloat16* __restrict__ al,
    const __nv_bfloat16* __restrict__ wh, const __nv_bfloat16* __restrict__ wl,
    const float* __restrict__ bias,
    float* __restrict__ y,
    __nv_bfloat16* __restrict__ oh, __nv_bfloat16* __restrict__ ol)
{
    extern __shared__ char smem[];
    const uint32_t sb = smem_u32(smem);
    const int tid  = threadIdx.x;
    const int wid  = tid >> 5;
    const int lane = tid & 31;
    const int g    = lane >> 2;         // 0..7
    const int tg   = lane & 3;          // 0..3
    const int b    = blockIdx.z;
    const int l0   = blockIdx.x * MT;
    const int co0  = blockIdx.y * NT;
    const int mBase = (wid & 3) * 32;   // warp M offset
    const int nBase = (wid >> 2) * 64;  // warp N offset

    // staging decomposition: idx 0..2047 -> tile pair (A rows / B rows)
    // A: 128 rows x 8 groups (h+l interleaved by 'part'), B same.
    const int sRow = tid >> 1;          // 0..127 (each thread does 1 row per tile kind? no)
    (void)sRow;

    float acc[2][8][4];
#pragma unroll
    for (int mf = 0; mf < 2; mf++)
#pragma unroll
        for (int nf = 0; nf < 8; nf++)
#pragma unroll
            for (int q = 0; q < 4; q++) acc[mf][nf][q] = 0.f;

    // ---- staging lambda (cp.async) ----
    auto stage = [&](int c, int s) {
        const uint32_t base = sb + s * STAGE_B;
        const int kappa0 = c * KC;
        const int seg = kappa0 / DD;
        const int ci0 = kappa0 - seg * DD;
        // A tiles: 128 rows x 8 x 16B  (h and l) -> 1024 copies per tile
        for (int idx = tid; idx < MT * 8; idx += CTT) {
            const int r = idx >> 3, gg = idx & 7;
            const int l = l0 + r + seg - 1;
            const int ok = ((unsigned)l < LL) ? 16 : 0;
            const size_t go = ((size_t)(b * LL + ((unsigned)l < LL ? l : 0))) * DD
                              + ci0 + gg * 8;
            const uint32_t so = r * 144 + gg * 16;
            CP16(base + SM_AH + so, ah + go, ok);
            CP16(base + SM_AL + so, al + go, ok);
        }
        // B tiles
        for (int idx = tid; idx < NT * 8; idx += CTT) {
            const int r = idx >> 3, gg = idx & 7;
            const size_t go = (size_t)(co0 + r) * KTOT + kappa0 + gg * 8;
            const uint32_t so = r * 144 + gg * 16;
            CP16(base + SM_BH + so, wh + go, 16);
            CP16(base + SM_BL + so, wl + go, 16);
        }
        CP_COMMIT();
    };

    stage(0, 0);

    for (int c = 0; c < NCHUNK; c++) {
        const int s = c & 1;
        if (c + 1 < NCHUNK) {
            stage(c + 1, s ^ 1);
            CP_WAIT(1);               // chunk c resident
        } else {
            CP_WAIT(0);
        }
        __syncthreads();

        const char* st = smem + s * STAGE_B;
        const uint32_t* Ah32 = reinterpret_cast<const uint32_t*>(st + SM_AH);
        const uint32_t* Al32 = reinterpret_cast<const uint32_t*>(st + SM_AL);
        const uint32_t* Bh32 = reinterpret_cast<const uint32_t*>(st + SM_BH);
        const uint32_t* Bl32 = reinterpret_cast<const uint32_t*>(st + SM_BL);

#pragma unroll
        for (int kk = 0; kk < 4; kk++) {            // K=16 steps in chunk
            const int kw = kk * 8 + tg;             // word offset in row
            uint32_t bh[8][2], bl[8][2];
#pragma unroll
            for (int nf = 0; nf < 8; nf++) {
                const int off = (nBase + nf * 8 + g) * 36 + kw;
                bh[nf][0] = Bh32[off];
                bh[nf][1] = Bh32[off + 4];
                bl[nf][0] = Bl32[off];
                bl[nf][1] = Bl32[off + 4];
            }
#pragma unroll
            for (int mf = 0; mf < 2; mf++) {
                const int m = mBase + mf * 16 + g;
                const int off  = m * 36 + kw;
                const int off8 = off + 8 * 36;
                const uint32_t a0 = Ah32[off],     a1 = Ah32[off8];
                const uint32_t a2 = Ah32[off + 4], a3 = Ah32[off8 + 4];
                const uint32_t c0 = Al32[off],     c1 = Al32[off8];
                const uint32_t c2 = Al32[off + 4], c3 = Al32[off8 + 4];
                // term-separated passes: dependent MMAs 8 issues apart
#pragma unroll
                for (int nf = 0; nf < 8; nf++)
                    MMA_BF16(acc[mf][nf], a0, a1, a2, a3, bh[nf][0], bh[nf][1]);
#pragma unroll
                for (int nf = 0; nf < 8; nf++)
                    MMA_BF16(acc[mf][nf], a0, a1, a2, a3, bl[nf][0], bl[nf][1]);
#pragma unroll
                for (int nf = 0; nf < 8; nf++)
                    MMA_BF16(acc[mf][nf], c0, c1, c2, c3, bh[nf][0], bh[nf][1]);
            }
        }
        __syncthreads();   // compute done before buffer s is restaged next iter
    }

    // ---- epilogue: bias + ReLU; optional fp32 / bf16-split stores ----
#pragma unroll
    for (int mf = 0; mf < 2; mf++) {
        const int m0 = mBase + mf * 16 + g;
        const size_t grow0 = ((size_t)(b * LL + l0 + m0)) * DD;
        const size_t grow1 = ((size_t)(b * LL + l0 + m0 + 8)) * DD;
#pragma unroll
        for (int nf = 0; nf < 8; nf++) {
            const int n0 = co0 + nBase + nf * 8 + tg * 2;
            const float bi0 = __ldg(bias + n0);
            const float bi1 = __ldg(bias + n0 + 1);
            float v0 = fmaxf(acc[mf][nf][0] + bi0, 0.f);
            float v1 = fmaxf(acc[mf][nf][1] + bi1, 0.f);
            float v2 = fmaxf(acc[mf][nf][2] + bi0, 0.f);
            float v3 = fmaxf(acc[mf][nf][3] + bi1, 0.f);
            if (y) {
                *reinterpret_cast<float2*>(y + grow0 + n0) = make_float2(v0, v1);
                *reinterpret_cast<float2*>(y + grow1 + n0) = make_float2(v2, v3);
            }
            if (oh) {
                __nv_bfloat16 h0, w0, h1, w1, h2, w2, h3, w3;
                bsplit(v0, h0, w0); bsplit(v1, h1, w1);
                bsplit(v2, h2, w2); bsplit(v3, h3, w3);
                uint32_t hw0 = (uint32_t)__bfloat16_as_ushort(h0) |
                               ((uint32_t)__bfloat16_as_ushort(h1) << 16);
                uint32_t lw0 = (uint32_t)__bfloat16_as_ushort(w0) |
                               ((uint32_t)__bfloat16_as_ushort(w1) << 16);
                uint32_t hw1 = (uint32_t)__bfloat16_as_ushort(h2) |
                               ((uint32_t)__bfloat16_as_ushort(h3) << 16);
                uint32_t lw1 = (uint32_t)__bfloat16_as_ushort(w2) |
                               ((uint32_t)__bfloat16_as_ushort(w3) << 16);
                *reinterpret_cast<uint32_t*>(oh + grow0 + n0) = hw0;
                *reinterpret_cast<uint32_t*>(ol + grow0 + n0) = lw0;
                *reinterpret_cast<uint32_t*>(oh + grow1 + n0) = hw1;
                *reinterpret_cast<uint32_t*>(ol + grow1 + n0) = lw1;
            }
        }
    }
}

// ---------------------------------------------------------------------------
// Split fp32 -> bf16 hi/lo (for initial x)
// ---------------------------------------------------------------------------
__global__ void split_kernel(const float* __restrict__ x,
                             __nv_bfloat16* __restrict__ oh,
                             __nv_bfloat16* __restrict__ ol, int n)
{
    int i = blockIdx.x * blockDim.x + threadIdx.x;
    if (i >= n) return;
    __nv_bfloat16 h, l;
    bsplit(x[i], h, l);
    oh[i] = h;
    ol[i] = l;
}

// ---------------------------------------------------------------------------
// Weight prep: w[co][ci][k] fp32 -> wh/wl[co][k*384+ci] bf16
// ---------------------------------------------------------------------------
__global__ void wsplit_kernel(const float* __restrict__ w,
                              __nv_bfloat16* __restrict__ wh,
                              __nv_bfloat16* __restrict__ wl)
{
    int idx = blockIdx.x * blockDim.x + threadIdx.x;
    if (idx >= DD * KTOT) return;
    int co = idx / KTOT;
    int kp = idx - co * KTOT;
    int k  = kp / DD;
    int ci = kp - k * DD;
    __nv_bfloat16 h, l;
    bsplit(w[co * KTOT + ci * KK + k], h, l);
    wh[idx] = h;
    wl[idx] = l;
}

// ---------------------------------------------------------------------------
// LayerNorm (D=384), one warp per row; optional fp32 out + bf16 hi/lo split.
// ---------------------------------------------------------------------------
__global__ __launch_bounds__(256) void ln_kernel(
    const float* __restrict__ x, const float* __restrict__ g,
    const float* __restrict__ beta, float* __restrict__ y,
    __nv_bfloat16* __restrict__ oh, __nv_bfloat16* __restrict__ ol)
{
    int row  = blockIdx.x * 8 + (threadIdx.x >> 5);
    int lane = threadIdx.x & 31;
    const float* xr = x + (size_t)row * DD;

    float v[12];
    float s = 0.f, s2 = 0.f;
#pragma unroll
    for (int i = 0; i < 12; i++) {
        v[i] = xr[lane + i * 32];
        s  += v[i];
        s2 += v[i] * v[i];
    }
#pragma unroll
    for (int o = 16; o; o >>= 1) {
        s  += __shfl_xor_sync(0xffffffffu, s, o);
        s2 += __shfl_xor_sync(0xffffffffu, s2, o);
    }
    const float inv = 1.f / (float)DD;
    float mu  = s * inv;
    float var = s2 * inv - mu * mu;
    float rs  = rsqrtf(var + 1e-5f);

    float* yr = y ? y + (size_t)row * DD : nullptr;
    __nv_bfloat16* hr = oh ? oh + (size_t)row * DD : nullptr;
    __nv_bfloat16* lr = ol ? ol + (size_t)row * DD : nullptr;
#pragma unroll
    for (int i = 0; i < 12; i++) {
        int c = lane + i * 32;
        float o2 = (v[i] - mu) * rs * g[c] + beta[c];
        if (yr) yr[c] = o2;
        if (hr) {
            __nv_bfloat16 h, l;
            bsplit(o2, h, l);
            hr[c] = h;
            lr[c] = l;
        }
    }
}

// ---------------------------------------------------------------------------
// Linear head: dur[row] = dot(h[row,:], w) + b. One warp per row.
// ---------------------------------------------------------------------------
__global__ __launch_bounds__(256) void lin_kernel(
    const float* __restrict__ h, const float* __restrict__ w,
    const float* __restrict__ bias, float* __restrict__ dur_out)
{
    int row  = blockIdx.x * 8 + (threadIdx.x >> 5);
    int lane = threadIdx.x & 31;
    const float* hr = h + (size_t)row * DD;
    float s = 0.f;
#pragma unroll
    for (int i = 0; i < 12; i++) {
        int c = lane + i * 32;
        s = fmaf(hr[c], w[c], s);
    }
#pragma unroll
    for (int o = 16; o; o >>= 1) s += __shfl_xor_sync(0xffffffffu, s, o);
    if (lane == 0) dur_out[row] = s + bias[0];
}

// ---------------------------------------------------------------------------
// Serial inclusive prefix scan: one thread per batch.
// ---------------------------------------------------------------------------
__global__ void serial_scan_kernel(const int* __restrict__ dur,
                                   int* __restrict__ cum,
                                   int* __restrict__ total)
{
    int b = threadIdx.x;
    if (b >= BB) return;
    int acc = 0;
    const int* dr = dur + b * LL;
    int* cr = cum + b * LL;
    for (int l = 0; l < LL; l++) {
        acc += dr[l];
        cr[l] = acc;
    }
    total[b] = acc;
}

// ---------------------------------------------------------------------------
// Length regulator scatter + tail zero (proven correct).
// ---------------------------------------------------------------------------
__global__ __launch_bounds__(128) void scatter_kernel(
    const float* __restrict__ x, const int* __restrict__ cum,
    float* __restrict__ out, int T)
{
    int l = blockIdx.x;
    int b = blockIdx.y;
    int lane = threadIdx.x;

    int end   = cum[b * LL + l];
    int start = (l == 0) ? 0 : cum[b * LL + l - 1];
    if (start == end) return;

    const float* xr = x + ((size_t)(b * LL + l)) * DD;
    float r0 = xr[lane];
    float r1 = xr[lane + 128];
    float r2 = xr[lane + 256];

    for (int t = start; t < end; t++) {
        float* o = out + ((size_t)b * T + t) * DD;
        o[lane]       = r0;
        o[lane + 128] = r1;
        o[lane + 256] = r2;
    }
}

__global__ __launch_bounds__(128) void zero_tail_kernel(
    const int* __restrict__ total, float* __restrict__ out, int T)
{
    int t = blockIdx.x;
    int b = blockIdx.y;
    if (t < total[b]) return;
    int lane = threadIdx.x;
    float* o = out + ((size_t)b * T + t) * DD;
    o[lane]       = 0.f;
    o[lane + 128] = 0.f;
    o[lane + 256] = 0.f;
}

// ---------------------------------------------------------------------------
extern "C" void kernel_launch(void* const* d_in, const int* in_sizes, int n_in,
                              void* d_out, int out_size)
{
    const float* x     = (const float*)d_in[0];
    const int*   dur   = (const int*)  d_in[1];
    const float* c1a_w = (const float*)d_in[2];
    const float* c1a_b = (const float*)d_in[3];
    const float* c1b_w = (const float*)d_in[4];
    const float* c1b_b = (const float*)d_in[5];
    const float* ln1_g = (const float*)d_in[6];
    const float* ln1_b = (const float*)d_in[7];
    const float* c2a_w = (const float*)d_in[8];
    const float* c2a_b = (const float*)d_in[9];
    const float* c2b_w = (const float*)d_in[10];
    const float* c2b_b = (const float*)d_in[11];
    const float* ln2_g = (const float*)d_in[12];
    const float* ln2_b = (const float*)d_in[13];
    const float* lin_w = (const float*)d_in[14];
    const float* lin_b = (const float*)d_in[15];
    float* out = (float*)d_out;

    long T = ((long)out_size - (long)BB * LL) / ((long)BB * DD);

    float *y0, *y1;
    __nv_bfloat16 *ah, *al, *bh, *bl, *wh, *wl;
    int *cum, *total;
    cudaGetSymbolAddress((void**)&y0,    g_y0);
    cudaGetSymbolAddress((void**)&y1,    g_y1);
    cudaGetSymbolAddress((void**)&ah,    g_ah);
    cudaGetSymbolAddress((void**)&al,    g_al);
    cudaGetSymbolAddress((void**)&bh,    g_bh);
    cudaGetSymbolAddress((void**)&bl,    g_bl);
    cudaGetSymbolAddress((void**)&wh,    g_wh);
    cudaGetSymbolAddress((void**)&wl,    g_wl);
    cudaGetSymbolAddress((void**)&cum,   g_cum);
    cudaGetSymbolAddress((void**)&total, g_total);

    cudaFuncSetAttribute(conv_mma_kernel,
                         cudaFuncAttributeMaxDynamicSharedMemorySize, SM_TOT);

    const int WN = DD * KTOT;
    const int n  = NROWS * DD;

    // Prep: operand splits
    split_kernel<<<(n + 255) / 256, 256>>>(x, ah, al, n);
    wsplit_kernel<<<(WN + 255) / 256, 256>>>(c1a_w, wh,          wl);
    wsplit_kernel<<<(WN + 255) / 256, 256>>>(c1b_w, wh + WN,     wl + WN);
    wsplit_kernel<<<(WN + 255) / 256, 256>>>(c2a_w, wh + 2 * WN, wl + 2 * WN);
    wsplit_kernel<<<(WN + 255) / 256, 256>>>(c2b_w, wh + 3 * WN, wl + 3 * WN);

    dim3 cgrid(LL / MT, DD / NT, BB);   // (4, 3, 32)

    // Duration predictor (HMMA tensor-core convs, cp.async pipelined)
    conv_mma_kernel<<<cgrid, CTT, SM_TOT>>>(ah, al, wh,          wl,          c1a_b,
                                            nullptr, bh, bl);
    conv_mma_kernel<<<cgrid, CTT, SM_TOT>>>(bh, bl, wh + WN,     wl + WN,     c1b_b,
                                            y0, nullptr, nullptr);
    ln_kernel<<<NROWS / 8, 256>>>(y0, ln1_g, ln1_b, nullptr, ah, al);
    conv_mma_kernel<<<cgrid, CTT, SM_TOT>>>(ah, al, wh + 2 * WN, wl + 2 * WN, c2a_b,
                                            nullptr, bh, bl);
    conv_mma_kernel<<<cgrid, CTT, SM_TOT>>>(bh, bl, wh + 3 * WN, wl + 3 * WN, c2b_b,
                                            y0, nullptr, nullptr);
    ln_kernel<<<NROWS / 8, 256>>>(y0, ln2_g, ln2_b, y1, nullptr, nullptr);
    lin_kernel<<<NROWS / 8, 256>>>(y1, lin_w, lin_b, out + (size_t)BB * T * DD);

    // Length regulator
    serial_scan_kernel<<<1, BB>>>(dur, cum, total);
    zero_tail_kernel<<<dim3((unsigned)T, BB), 128>>>(total, out, (int)T);
    scatter_kernel<<<dim3(LL, BB), 128>>>(x, cum, out, (int)T);
}

// round 7
// speedup vs baseline: 3.8761x; 1.0120x over previous
#include <cuda_runtime.h>
#include <cuda_bf16.h>
#include <cstdint>

// Problem constants
#define BB 32
#define LL 512
#define DD 384
#define KK 3
#define KTOT (DD * KK)        // 1152 GEMM-K
#define NROWS (BB * LL)       // 16384 GEMM-M

// Conv MMA tiling
#define MT 128                // M rows per CTA (L-tile)
#define NT 128                // N cols per CTA (c_out tile)
#define KC 64                 // K chunk
#define NCHUNK (KTOT / KC)    // 18
#define CTT 256               // 8 warps

// smem per stage:
//   A tiles (row-major, 128 rows x 72 halves = 144B rows): 18432B each (h,l)
//   B tiles (k-major,  64 rows x 136 halves = 272B rows): 17408B each (h,l)
#define A_TILE_B 18432
#define B_TILE_B 17408
#define SM_AH 0
#define SM_AL A_TILE_B
#define SM_BH (2 * A_TILE_B)
#define SM_BL (2 * A_TILE_B + B_TILE_B)
#define STAGE_B (2 * A_TILE_B + 2 * B_TILE_B)   // 71680
#define SM_TOT (3 * STAGE_B)                     // 215040

// ---------------- device scratch (allocation-free) -------------------------
__device__ float g_y0[NROWS * DD];
__device__ __align__(16) __nv_bfloat16 g_ah[NROWS * DD];
__device__ __align__(16) __nv_bfloat16 g_al[NROWS * DD];
__device__ __align__(16) __nv_bfloat16 g_bh[NROWS * DD];
__device__ __align__(16) __nv_bfloat16 g_bl[NROWS * DD];
__device__ __align__(16) __nv_bfloat16 g_wh[4][KTOT * DD];  // [kappa][co]
__device__ __align__(16) __nv_bfloat16 g_wl[4][KTOT * DD];
__device__ int g_cum[BB * LL];
__device__ int g_total[BB];

// ---------------- helpers --------------------------------------------------
__device__ __forceinline__ void bsplit(float v, __nv_bfloat16& h, __nv_bfloat16& l) {
    h = __float2bfloat16_rn(v);
    l = __float2bfloat16_rn(v - __bfloat162float(h));
}
__device__ __forceinline__ uint32_t smem_u32(const void* p) {
    uint32_t a;
    asm("{ .reg .u64 t; cvta.to.shared.u64 t, %1; cvt.u32.u64 %0, t; }"
        : "=r"(a) : "l"(p));
    return a;
}

#define CP16(dst, src, sz)                                                     \
    asm volatile("cp.async.cg.shared.global [%0], [%1], 16, %2;"               \
                 :: "r"(dst), "l"(src), "r"(sz) : "memory")
#define CP_COMMIT()  asm volatile("cp.async.commit_group;" ::: "memory")
#define CP_WAIT(n)   asm volatile("cp.async.wait_group %0;" :: "n"(n) : "memory")

#define MMA_BF16(c, a0, a1, a2, a3, b0, b1)                                    \
    asm volatile(                                                              \
        "mma.sync.aligned.m16n8k16.row.col.f32.bf16.bf16.f32 "                 \
        "{%0,%1,%2,%3},{%4,%5,%6,%7},{%8,%9},{%0,%1,%2,%3};"                   \
        : "+f"((c)[0]), "+f"((c)[1]), "+f"((c)[2]), "+f"((c)[3])               \
        : "r"(a0), "r"(a1), "r"(a2), "r"(a3), "r"(b0), "r"(b1))

#define LDSM4(r0, r1, r2, r3, addr)                                            \
    asm volatile("ldmatrix.sync.aligned.m8n8.x4.shared.b16 {%0,%1,%2,%3}, [%4];" \
        : "=r"(r0), "=r"(r1), "=r"(r2), "=r"(r3) : "r"(addr))
#define LDSM4T(r0, r1, r2, r3, addr)                                           \
    asm volatile("ldmatrix.sync.aligned.m8n8.x4.trans.shared.b16 {%0,%1,%2,%3}, [%4];" \
        : "=r"(r0), "=r"(r1), "=r"(r2), "=r"(r3) : "r"(addr))

// ---------------------------------------------------------------------------
// Conv1D(K=3,SAME)+bias+ReLU as HMMA bf16 GEMM with 3-term bf16 splitting.
// 3-stage cp.async pipeline, ldmatrix fragment loads.
// A: [row][k] 144B rows. B: [k][co] 272B rows (k-major, from transposed w).
// Grid (4 Lt, 3 Nt, 32 b), 256 threads.
// ---------------------------------------------------------------------------
__global__ __launch_bounds__(CTT, 1) void conv_mma_kernel(
    const __nv_bfloat16* __restrict__ ah, const __nv_bfloat16* __restrict__ al,
    const __nv_bfloat16* __restrict__ wh, const __nv_bfloat16* __restrict__ wl,
    const float* __restrict__ bias,
    float* __restrict__ y,
    __nv_bfloat16* __restrict__ oh, __nv_bfloat16* __restrict__ ol)
{
    extern __shared__ char smem[];
    const uint32_t sb = smem_u32(smem);
    const int tid  = threadIdx.x;
    const int wid  = tid >> 5;
    const int lane = tid & 31;
    const int g    = lane >> 2;         // 0..7
    const int tg   = lane & 3;          // 0..3
    const int b    = blockIdx.z;
    const int l0   = blockIdx.x * MT;
    const int co0  = blockIdx.y * NT;
    const int mBase = (wid & 3) * 32;   // warp M offset
    const int nBase = (wid >> 2) * 64;  // warp N offset

    // ldmatrix lane-address components
    const int aRowSel = lane & 15;           // row within 16 (m)
    const int aColSel = (lane >> 4) * 16;    // +16B for k8 half
    const int bKSel   = ((lane >> 3) & 1) * 8 + (lane & 7);  // k row within 16
    const int bNSel   = (lane >> 4) * 8;     // +8 n for second nf

    float acc[2][8][4];
#pragma unroll
    for (int mf = 0; mf < 2; mf++)
#pragma unroll
        for (int nf = 0; nf < 8; nf++)
#pragma unroll
            for (int q = 0; q < 4; q++) acc[mf][nf][q] = 0.f;

    // ---- staging (cp.async) ----
    auto stage = [&](int c, int s) {
        const uint32_t base = sb + s * STAGE_B;
        const int kappa0 = c * KC;
        const int seg = kappa0 / DD;
        const int ci0 = kappa0 - seg * DD;
        // A tiles: 128 rows x 8 x 16B (h and l), shifted by seg-1, zfill halo
        for (int idx = tid; idx < MT * 8; idx += CTT) {
            const int r = idx >> 3, gg = idx & 7;
            const int l = l0 + r + seg - 1;
            const int ok = ((unsigned)l < LL) ? 16 : 0;
            const size_t go = ((size_t)(b * LL + ((unsigned)l < LL ? l : 0))) * DD
                              + ci0 + gg * 8;
            const uint32_t so = r * 144 + gg * 16;
            CP16(base + SM_AH + so, ah + go, ok);
            CP16(base + SM_AL + so, al + go, ok);
        }
        // B tiles: 64 k-rows x 16 x 16B (h and l); gmem wh is [kappa][co]
        for (int idx = tid; idx < KC * 16; idx += CTT) {
            const int kr = idx >> 4, gg = idx & 15;
            const size_t go = (size_t)(kappa0 + kr) * DD + co0 + gg * 8;
            const uint32_t so = kr * 272 + gg * 16;
            CP16(base + SM_BH + so, wh + go, 16);
            CP16(base + SM_BL + so, wl + go, 16);
        }
        CP_COMMIT();
    };

    stage(0, 0);
    stage(1, 1);

    int s = 0;
    for (int c = 0; c < NCHUNK; c++) {
        if (c + 2 < NCHUNK) {
            stage(c + 2, (c + 2) % 3);
            CP_WAIT(2);
        } else if (c + 1 < NCHUNK) {
            CP_WAIT(1);
        } else {
            CP_WAIT(0);
        }
        __syncthreads();

        const uint32_t stA = sb + s * STAGE_B + SM_AH;
        const uint32_t stB = sb + s * STAGE_B + SM_BH;

#pragma unroll
        for (int kk = 0; kk < 4; kk++) {            // K=16 steps in chunk
            // B fragments via ldmatrix.x4.trans (k-major rows)
            uint32_t bh[8][2], bl[8][2];
#pragma unroll
            for (int p = 0; p < 4; p++) {
                const uint32_t bad = stB + (kk * 16 + bKSel) * 272
                                   + (nBase + p * 16 + bNSel) * 2;
                LDSM4T(bh[p * 2][0], bh[p * 2][1],
                       bh[p * 2 + 1][0], bh[p * 2 + 1][1], bad);
                LDSM4T(bl[p * 2][0], bl[p * 2][1],
                       bl[p * 2 + 1][0], bl[p * 2 + 1][1], bad + B_TILE_B);
            }
#pragma unroll
            for (int mf = 0; mf < 2; mf++) {
                const uint32_t aad = stA + (mBase + mf * 16 + aRowSel) * 144
                                   + kk * 32 + aColSel;
                uint32_t a0, a1, a2, a3, c0, c1, c2, c3;
                LDSM4(a0, a1, a2, a3, aad);
                LDSM4(c0, c1, c2, c3, aad + A_TILE_B);
                // term-separated passes: dependent MMAs 8 issues apart
#pragma unroll
                for (int nf = 0; nf < 8; nf++)
                    MMA_BF16(acc[mf][nf], a0, a1, a2, a3, bh[nf][0], bh[nf][1]);
#pragma unroll
                for (int nf = 0; nf < 8; nf++)
                    MMA_BF16(acc[mf][nf], a0, a1, a2, a3, bl[nf][0], bl[nf][1]);
#pragma unroll
                for (int nf = 0; nf < 8; nf++)
                    MMA_BF16(acc[mf][nf], c0, c1, c2, c3, bh[nf][0], bh[nf][1]);
            }
        }
        __syncthreads();   // compute done before buffer s is restaged
        s = (s + 1) % 3;
    }

    // ---- epilogue: bias + ReLU; optional fp32 / bf16-split stores ----
#pragma unroll
    for (int mf = 0; mf < 2; mf++) {
        const int m0 = mBase + mf * 16 + g;
        const size_t grow0 = ((size_t)(b * LL + l0 + m0)) * DD;
        const size_t grow1 = ((size_t)(b * LL + l0 + m0 + 8)) * DD;
#pragma unroll
        for (int nf = 0; nf < 8; nf++) {
            const int n0 = co0 + nBase + nf * 8 + tg * 2;
            const float bi0 = __ldg(bias + n0);
            const float bi1 = __ldg(bias + n0 + 1);
            float v0 = fmaxf(acc[mf][nf][0] + bi0, 0.f);
            float v1 = fmaxf(acc[mf][nf][1] + bi1, 0.f);
            float v2 = fmaxf(acc[mf][nf][2] + bi0, 0.f);
            float v3 = fmaxf(acc[mf][nf][3] + bi1, 0.f);
            if (y) {
                *reinterpret_cast<float2*>(y + grow0 + n0) = make_float2(v0, v1);
                *reinterpret_cast<float2*>(y + grow1 + n0) = make_float2(v2, v3);
            }
            if (oh) {
                __nv_bfloat16 h0, w0, h1, w1, h2, w2, h3, w3;
                bsplit(v0, h0, w0); bsplit(v1, h1, w1);
                bsplit(v2, h2, w2); bsplit(v3, h3, w3);
                uint32_t hw0 = (uint32_t)__bfloat16_as_ushort(h0) |
                               ((uint32_t)__bfloat16_as_ushort(h1) << 16);
                uint32_t lw0 = (uint32_t)__bfloat16_as_ushort(w0) |
                               ((uint32_t)__bfloat16_as_ushort(w1) << 16);
                uint32_t hw1 = (uint32_t)__bfloat16_as_ushort(h2) |
                               ((uint32_t)__bfloat16_as_ushort(h3) << 16);
                uint32_t lw1 = (uint32_t)__bfloat16_as_ushort(w2) |
                               ((uint32_t)__bfloat16_as_ushort(w3) << 16);
                *reinterpret_cast<uint32_t*>(oh + grow0 + n0) = hw0;
                *reinterpret_cast<uint32_t*>(ol + grow0 + n0) = lw0;
                *reinterpret_cast<uint32_t*>(oh + grow1 + n0) = hw1;
                *reinterpret_cast<uint32_t*>(ol + grow1 + n0) = lw1;
            }
        }
    }
}

// ---------------------------------------------------------------------------
// Split fp32 -> bf16 hi/lo (for initial x)
// ---------------------------------------------------------------------------
__global__ void split_kernel(const float* __restrict__ x,
                             __nv_bfloat16* __restrict__ oh,
                             __nv_bfloat16* __restrict__ ol, int n)
{
    int i = blockIdx.x * blockDim.x + threadIdx.x;
    if (i >= n) return;
    __nv_bfloat16 h, l;
    bsplit(x[i], h, l);
    oh[i] = h;
    ol[i] = l;
}

// ---------------------------------------------------------------------------
// Weight prep: w[co][ci][k] fp32 -> wh/wl[kappa][co] bf16 (kappa = k*384+ci),
// via smem-tiled transpose. Block (32,8), grid (KTOT/32, DD/32).
// 384 % 32 == 0, so a kappa-tile never straddles a tap boundary.
// ---------------------------------------------------------------------------
__global__ void wsplitT_kernel(const float* __restrict__ w,
                               __nv_bfloat16* __restrict__ wh,
                               __nv_bfloat16* __restrict__ wl)
{
    __shared__ float t[32][33];
    const int ka0 = blockIdx.x * 32;
    const int co0 = blockIdx.y * 32;
    const int tx = threadIdx.x, ty = threadIdx.y;
    const int k   = ka0 / DD;
    const int ci0 = ka0 - k * DD;

#pragma unroll
    for (int i = 0; i < 32; i += 8) {
        const int co = co0 + ty + i;
        const int ci = ci0 + tx;
        t[ty + i][tx] = w[(size_t)co * KTOT + ci * KK + k];
    }
    __syncthreads();
#pragma unroll
    for (int i = 0; i < 32; i += 8) {
        const int ka = ka0 + ty + i;
        const int co = co0 + tx;
        __nv_bfloat16 h, l;
        bsplit(t[tx][ty + i], h, l);
        wh[(size_t)ka * DD + co] = h;
        wl[(size_t)ka * DD + co] = l;
    }
}

// ---------------------------------------------------------------------------
// LayerNorm (D=384), one warp per row; optional bf16 hi/lo split out and
// optional fused linear head (dur[row] = dot(o, lin_w) + lin_b).
// ---------------------------------------------------------------------------
__global__ __launch_bounds__(256) void ln_kernel(
    const float* __restrict__ x, const float* __restrict__ g,
    const float* __restrict__ beta,
    __nv_bfloat16* __restrict__ oh, __nv_bfloat16* __restrict__ ol,
    const float* __restrict__ lw, const float* __restrict__ lb,
    float* __restrict__ dur_out)
{
    int row  = blockIdx.x * 8 + (threadIdx.x >> 5);
    int lane = threadIdx.x & 31;
    const float* xr = x + (size_t)row * DD;

    float v[12];
    float s = 0.f, s2 = 0.f;
#pragma unroll
    for (int i = 0; i < 12; i++) {
        v[i] = xr[lane + i * 32];
        s  += v[i];
        s2 += v[i] * v[i];
    }
#pragma unroll
    for (int o = 16; o; o >>= 1) {
        s  += __shfl_xor_sync(0xffffffffu, s, o);
        s2 += __shfl_xor_sync(0xffffffffu, s2, o);
    }
    const float inv = 1.f / (float)DD;
    float mu  = s * inv;
    float var = s2 * inv - mu * mu;
    float rs  = rsqrtf(var + 1e-5f);

    __nv_bfloat16* hr = oh ? oh + (size_t)row * DD : nullptr;
    __nv_bfloat16* lr = ol ? ol + (size_t)row * DD : nullptr;
    float dsum = 0.f;
#pragma unroll
    for (int i = 0; i < 12; i++) {
        int c = lane + i * 32;
        float o2 = (v[i] - mu) * rs * g[c] + beta[c];
        if (hr) {
            __nv_bfloat16 h, l;
            bsplit(o2, h, l);
            hr[c] = h;
            lr[c] = l;
        }
        if (dur_out) dsum = fmaf(o2, lw[c], dsum);
    }
    if (dur_out) {
#pragma unroll
        for (int o = 16; o; o >>= 1) dsum += __shfl_xor_sync(0xffffffffu, dsum, o);
        if (lane == 0) dur_out[row] = dsum + lb[0];
    }
}

// ---------------------------------------------------------------------------
// Serial inclusive prefix scan: one thread per batch.
// ---------------------------------------------------------------------------
__global__ void serial_scan_kernel(const int* __restrict__ dur,
                                   int* __restrict__ cum,
                                   int* __restrict__ total)
{
    int b = threadIdx.x;
    if (b >= BB) return;
    int acc = 0;
    const int* dr = dur + b * LL;
    int* cr = cum + b * LL;
    for (int l = 0; l < LL; l++) {
        acc += dr[l];
        cr[l] = acc;
    }
    total[b] = acc;
}

// ---------------------------------------------------------------------------
// Length regulator scatter + tail zero (proven correct).
// ---------------------------------------------------------------------------
__global__ __launch_bounds__(128) void scatter_kernel(
    const float* __restrict__ x, const int* __restrict__ cum,
    float* __restrict__ out, int T)
{
    int l = blockIdx.x;
    int b = blockIdx.y;
    int lane = threadIdx.x;

    int end   = cum[b * LL + l];
    int start = (l == 0) ? 0 : cum[b * LL + l - 1];
    if (start == end) return;

    const float* xr = x + ((size_t)(b * LL + l)) * DD;
    float r0 = xr[lane];
    float r1 = xr[lane + 128];
    float r2 = xr[lane + 256];

    for (int t = start; t < end; t++) {
        float* o = out + ((size_t)b * T + t) * DD;
        o[lane]       = r0;
        o[lane + 128] = r1;
        o[lane + 256] = r2;
    }
}

__global__ __launch_bounds__(128) void zero_tail_kernel(
    const int* __restrict__ total, float* __restrict__ out, int T)
{
    int t = blockIdx.x;
    int b = blockIdx.y;
    if (t < total[b]) return;
    int lane = threadIdx.x;
    float* o = out + ((size_t)b * T + t) * DD;
    o[lane]       = 0.f;
    o[lane + 128] = 0.f;
    o[lane + 256] = 0.f;
}

// ---------------------------------------------------------------------------
extern "C" void kernel_launch(void* const* d_in, const int* in_sizes, int n_in,
                              void* d_out, int out_size)
{
    const float* x     = (const float*)d_in[0];
    const int*   dur   = (const int*)  d_in[1];
    const float* c1a_w = (const float*)d_in[2];
    const float* c1a_b = (const float*)d_in[3];
    const float* c1b_w = (const float*)d_in[4];
    const float* c1b_b = (const float*)d_in[5];
    const float* ln1_g = (const float*)d_in[6];
    const float* ln1_b = (const float*)d_in[7];
    const float* c2a_w = (const float*)d_in[8];
    const float* c2a_b = (const float*)d_in[9];
    const float* c2b_w = (const float*)d_in[10];
    const float* c2b_b = (const float*)d_in[11];
    const float* ln2_g = (const float*)d_in[12];
    const float* ln2_b = (const float*)d_in[13];
    const float* lin_w = (const float*)d_in[14];
    const float* lin_b = (const float*)d_in[15];
    float* out = (float*)d_out;

    long T = ((long)out_size - (long)BB * LL) / ((long)BB * DD);

    float *y0;
    __nv_bfloat16 *ah, *al, *bh, *bl, *wh, *wl;
    int *cum, *total;
    cudaGetSymbolAddress((void**)&y0,    g_y0);
    cudaGetSymbolAddress((void**)&ah,    g_ah);
    cudaGetSymbolAddress((void**)&al,    g_al);
    cudaGetSymbolAddress((void**)&bh,    g_bh);
    cudaGetSymbolAddress((void**)&bl,    g_bl);
    cudaGetSymbolAddress((void**)&wh,    g_wh);
    cudaGetSymbolAddress((void**)&wl,    g_wl);
    cudaGetSymbolAddress((void**)&cum,   g_cum);
    cudaGetSymbolAddress((void**)&total, g_total);

    cudaFuncSetAttribute(conv_mma_kernel,
                         cudaFuncAttributeMaxDynamicSharedMemorySize, SM_TOT);

    const int WN = KTOT * DD;
    const int n  = NROWS * DD;

    // Prep: operand splits (weights transposed to [kappa][co])
    split_kernel<<<(n + 255) / 256, 256>>>(x, ah, al, n);
    dim3 wtg(KTOT / 32, DD / 32);
    dim3 wtb(32, 8);
    wsplitT_kernel<<<wtg, wtb>>>(c1a_w, wh,          wl);
    wsplitT_kernel<<<wtg, wtb>>>(c1b_w, wh + WN,     wl + WN);
    wsplitT_kernel<<<wtg, wtb>>>(c2a_w, wh + 2 * WN, wl + 2 * WN);
    wsplitT_kernel<<<wtg, wtb>>>(c2b_w, wh + 3 * WN, wl + 3 * WN);

    dim3 cgrid(LL / MT, DD / NT, BB);   // (4, 3, 32)

    // Duration predictor (HMMA convs, ldmatrix + 3-stage cp.async)
    conv_mma_kernel<<<cgrid, CTT, SM_TOT>>>(ah, al, wh,          wl,          c1a_b,
                                            nullptr, bh, bl);
    conv_mma_kernel<<<cgrid, CTT, SM_TOT>>>(bh, bl, wh + WN,     wl + WN,     c1b_b,
                                            y0, nullptr, nullptr);
    ln_kernel<<<NROWS / 8, 256>>>(y0, ln1_g, ln1_b, ah, al,
                                  nullptr, nullptr, nullptr);
    conv_mma_kernel<<<cgrid, CTT, SM_TOT>>>(ah, al, wh + 2 * WN, wl + 2 * WN, c2a_b,
                                            nullptr, bh, bl);
    conv_mma_kernel<<<cgrid, CTT, SM_TOT>>>(bh, bl, wh + 3 * WN, wl + 3 * WN, c2b_b,
                                            y0, nullptr, nullptr);
    // fused LN2 + linear head
    ln_kernel<<<NROWS / 8, 256>>>(y0, ln2_g, ln2_b, nullptr, nullptr,
                                  lin_w, lin_b, out + (size_t)BB * T * DD);

    // Length regulator
    serial_scan_kernel<<<1, BB>>>(dur, cum, total);
    zero_tail_kernel<<<dim3((unsigned)T, BB), 128>>>(total, out, (int)T);
    scatter_kernel<<<dim3(LL, BB), 128>>>(x, cum, out, (int)T);
}